// round 3
// baseline (speedup 1.0000x reference)
#include <cuda_runtime.h>

typedef unsigned long long u64;

#define B  32
#define P  16384
#define O  16
#define NC 80
#define TOTAL4 (B * P * (NC / 4))      // 10,485,760 float4 of conf

// ---------------- device scratch (no allocations allowed) ----------------
__device__ float         g_overlap[B * P];   // pre-override best IoU (for patch)
__device__ int           g_bidx[B * P];      // pre-override best truth (for patch)
__device__ unsigned char g_valid[B * P];
__device__ u64           g_bestprior[B * O];
__device__ float         g_sum_ll;           // loc loss sum
__device__ float         g_sum_lcraw;        // sum of sigmoid*softplus (t=0 form, no 0.75)
__device__ float         g_sum_corr;         // target-class corrections (true units)
__device__ int           g_poscnt;

// ---------------- f32x2 packed helpers ----------------
__device__ __forceinline__ u64 pack2(float lo, float hi) {
    u64 r; asm("mov.b64 %0, {%1, %2};" : "=l"(r) : "f"(lo), "f"(hi)); return r;
}
__device__ __forceinline__ void unpack2(u64 v, float& lo, float& hi) {
    asm("mov.b64 {%0, %1}, %2;" : "=f"(lo), "=f"(hi) : "l"(v));
}
__device__ __forceinline__ u64 fma2(u64 a, u64 b, u64 c) {
    u64 d; asm("fma.rn.f32x2 %0, %1, %2, %3;" : "=l"(d) : "l"(a), "l"(b), "l"(c)); return d;
}
__device__ __forceinline__ u64 mul2(u64 a, u64 b) {
    u64 d; asm("mul.rn.f32x2 %0, %1, %2;" : "=l"(d) : "l"(a), "l"(b)); return d;
}
__device__ __forceinline__ u64 add2(u64 a, u64 b) {
    u64 d; asm("add.rn.f32x2 %0, %1, %2;" : "=l"(d) : "l"(a), "l"(b)); return d;
}
__device__ __forceinline__ float frcp(float a) {
    float r; asm("rcp.approx.f32 %0, %1;" : "=f"(r) : "f"(a)); return r;
}

// A&S 4.1.43: ln(1+s) = s*(A1 + s*(A2 + s*(A3 + s*(A4 + s*A5)))), |err|<=1e-5 on [0,1]
#define LA1 0.99949556f
#define LA2 (-0.49190896f)
#define LA3 0.28947478f
#define LA4 (-0.13606275f)
#define LA5 0.03215845f

// packed g0 accumulate: acc += g0(x0) + g0(x1), g0(x) = softplus(x)*sigmoid(x)
// 2 MUFU per element (ex2 + rcp), FMA chain packed f32x2, selects/max on ALU pipe.
__device__ __forceinline__ u64 g0pair_acc(float x0, float x1, u64 acc,
                                          u64 CA1, u64 CA2, u64 CA3, u64 CA4, u64 CA5,
                                          u64 ONE2) {
    float s0 = __expf(-fabsf(x0));
    float s1 = __expf(-fabsf(x1));
    u64 s = pack2(s0, s1);
    u64 u = add2(s, ONE2);                        // 1 + s
    float u0, u1; unpack2(u, u0, u1);
    float r0 = frcp(u0), r1 = frcp(u1);
    float n0 = (x0 >= 0.f) ? s0 : 1.0f;           // FSEL (alu)
    float n1 = (x1 >= 0.f) ? s1 : 1.0f;
    u64 q = mul2(pack2(n0, n1), pack2(r0, r1));   // sigmoid(-x)
    // L = log1p(s) via packed Horner
    u64 pl = fma2(s, CA5, CA4);
    pl = fma2(s, pl, CA3);
    pl = fma2(s, pl, CA2);
    pl = fma2(s, pl, CA1);
    u64 L = mul2(pl, s);
    u64 m = pack2(fmaxf(x0, 0.f), fmaxf(x1, 0.f)); // FMNMX (alu)
    u64 h = add2(m, L);                            // softplus(x)
    u64 nq = q ^ 0x8000000080000000ull;            // -q (sign flip, alu)
    // acc += h*(1-q)  ==  (h + acc) + h*(-q)
    return fma2(h, nq, add2(h, acc));
}

// ---------------- precise helpers (cold paths) ----------------
__device__ __forceinline__ float g0raw(float x) {   // sigmoid(x)*softplus(x), precise
    float e = __expf(-fabsf(x));
    float L = __logf(1.0f + e);
    float h = fmaxf(x, 0.0f) + L;
    float q = __expf(-h);
    return fmaf(-h, q, h);
}

__device__ __forceinline__ float bl1(float diff) {
    const float bb = 19.085537f;                    // e^3 - 1
    float d = fabsf(diff);
    if (d < 0.11f) {
        return (0.5f / bb) * (bb * d + 1.f) * log1pf(bb * d * (1.0f / 0.11f)) - 0.5f * d;
    }
    return 1.5f * d + (1.5f / bb - 0.5f * 0.11f);
}

// loc loss + focal target-class correction for a positive prior (b, prior p, truth j)
__device__ __forceinline__ void pos_meta(int b, int j, int p, int bp,
                                         const float4* __restrict__ priors,
                                         const float*  __restrict__ targets,
                                         const float*  __restrict__ conf,
                                         const float4* __restrict__ loc4,
                                         float& ll, float& corr) {
    const float* t = targets + (b * O + j) * 5;
    float m0 = t[0], m1 = t[1], m2 = t[2], m3 = t[3];
    int tc = (int)t[4] + 1;                         // 1..80
    float4 pp = priors[p];
    float ex = ((m0 + m2) * 0.5f - pp.x) / (0.1f * pp.z);
    float ey = ((m1 + m3) * 0.5f - pp.y) / (0.1f * pp.w);
    float ew = __logf((m2 - m0) / pp.z) * 5.0f;
    float eh = __logf((m3 - m1) / pp.w) * 5.0f;
    float4 ld = loc4[bp];
    ll = bl1(ld.x - ex) + bl1(ld.y - ey) + bl1(ld.z - ew) + bl1(ld.w - eh);
    float x = conf[bp * NC + (tc - 1)];
    corr = 0.25f * g0raw(-x) - 0.75f * g0raw(x);    // focal(x,1) - focal(x,0)
}

// ---------------- kernels ----------------
// match + per-prior meta fused. grid = (P/256, B)
__global__ void k_match(const float4* __restrict__ priors,
                        const float*  __restrict__ targets,
                        const float*  __restrict__ conf,
                        const float4* __restrict__ loc4) {
    __shared__ float4 s_tr[O];
    __shared__ float  s_area[O];
    __shared__ u64    s_key[O];

    int tid = threadIdx.x;
    int b   = blockIdx.y;
    int p   = blockIdx.x * blockDim.x + tid;

    if (tid < O) {
        const float* t = targets + (b * O + tid) * 5;
        float4 tr = make_float4(t[0], t[1], t[2], t[3]);
        s_tr[tid]   = tr;
        s_area[tid] = (tr.z - tr.x) * (tr.w - tr.y);
        s_key[tid]  = 0ull;
    }
    __syncthreads();

    float4 pr = priors[p];
    float px0 = pr.x - pr.z * 0.5f;
    float py0 = pr.y - pr.w * 0.5f;
    float px1 = pr.x + pr.z * 0.5f;
    float py1 = pr.y + pr.w * 0.5f;
    float areaB = (px1 - px0) * (py1 - py0);

    float best = -1.f;
    int   bidx = 0;
    #pragma unroll
    for (int j = 0; j < O; j++) {
        float4 tr = s_tr[j];
        float ix = fmaxf(fminf(tr.z, px1) - fmaxf(tr.x, px0), 0.f);
        float iy = fmaxf(fminf(tr.w, py1) - fmaxf(tr.y, py0), 0.f);
        float inter = ix * iy;
        float iou   = inter / (s_area[j] + areaB - inter);
        if (iou > best) { best = iou; bidx = j; }   // first-max (JAX argmax)
        u64 key = ((u64)__float_as_uint(iou) << 32) |
                  (unsigned)(0xFFFFFFFFu - (unsigned)p);   // ties -> smallest p
        if (key > s_key[j]) atomicMax(&s_key[j], key);
    }

    int bp = b * P + p;
    g_overlap[bp] = best;
    g_bidx[bp]    = bidx;

    bool pos   = best >= 0.5f;
    bool valid = pos || (best < 0.4f);
    g_valid[bp] = valid ? 1 : 0;

    float ll = 0.f, corr = 0.f;
    int pc = 0;
    if (pos) {
        pc = 1;
        pos_meta(b, bidx, p, bp, priors, targets, conf, loc4, ll, corr);
    }

    // block reduction of ll / corr / pc
    #pragma unroll
    for (int o = 16; o; o >>= 1) {
        ll   += __shfl_down_sync(0xFFFFFFFFu, ll, o);
        corr += __shfl_down_sync(0xFFFFFFFFu, corr, o);
        pc   += __shfl_down_sync(0xFFFFFFFFu, pc, o);
    }
    __shared__ float s_ll[8], s_co[8];
    __shared__ int   s_pc[8];
    int wid = tid >> 5, lane = tid & 31;
    if (lane == 0) { s_ll[wid] = ll; s_co[wid] = corr; s_pc[wid] = pc; }
    __syncthreads();
    if (wid == 0) {
        ll   = (lane < 8) ? s_ll[lane] : 0.f;
        corr = (lane < 8) ? s_co[lane] : 0.f;
        pc   = (lane < 8) ? s_pc[lane] : 0;
        #pragma unroll
        for (int o = 4; o; o >>= 1) {
            ll   += __shfl_down_sync(0xFFFFFFFFu, ll, o);
            corr += __shfl_down_sync(0xFFFFFFFFu, corr, o);
            pc   += __shfl_down_sync(0xFFFFFFFFu, pc, o);
        }
        if (lane == 0 && pc) {
            atomicAdd(&g_sum_ll, ll);
            atomicAdd(&g_sum_corr, corr);
            atomicAdd(&g_poscnt, pc);
        }
    }

    // flush per-truth best-prior keys
    if (tid < O) {
        u64 key = s_key[tid];
        if (key > g_bestprior[b * O + tid]) atomicMax(&g_bestprior[b * O + tid], key);
    }
}

// force-match patch: delta-correct sums for each truth's best prior (last-wins dedup)
__global__ void k_patch(const float4* __restrict__ priors,
                        const float*  __restrict__ targets,
                        const float*  __restrict__ conf,
                        const float4* __restrict__ loc4) {
    int tid = threadIdx.x;             // 512 = B*O
    int b = tid >> 4, j = tid & 15;
    u64 key = g_bestprior[b * O + j];
    unsigned p = 0xFFFFFFFFu - (unsigned)(key & 0xFFFFFFFFull);

    __shared__ unsigned s_p[B * O];
    s_p[tid] = p;
    __syncthreads();

    bool apply = true;                 // XLA scatter: last truth targeting p wins
    for (int j2 = j + 1; j2 < O; j2++)
        if (s_p[(b << 4) | j2] == p) apply = false;

    if (apply) {
        int bp = b * P + (int)p;
        float oldov = g_overlap[bp];
        int   oldj  = g_bidx[bp];
        bool  oldpos = oldov >= 0.5f;
        g_valid[bp] = 1;               // forced positive -> always valid

        float ll_n, corr_n;
        pos_meta(b, j, (int)p, bp, priors, targets, conf, loc4, ll_n, corr_n);
        float dll = ll_n, dcorr = corr_n;
        int dpc = 1;
        if (oldpos) {                  // remove the contribution k_match already added
            float ll_o, corr_o;
            pos_meta(b, oldj, (int)p, bp, priors, targets, conf, loc4, ll_o, corr_o);
            dll -= ll_o; dcorr -= corr_o; dpc = 0;
        }
        atomicAdd(&g_sum_ll, dll);
        atomicAdd(&g_sum_corr, dcorr);
        if (dpc) atomicAdd(&g_poscnt, dpc);
    }
}

// streaming focal: all valid elements as t=0, 2 MUFU/elem + packed f32x2 FMA chain
__global__ void __launch_bounds__(256) k_loss(const float4* __restrict__ conf4) {
    const u64 CA1 = pack2(LA1, LA1), CA2 = pack2(LA2, LA2), CA3 = pack2(LA3, LA3),
              CA4 = pack2(LA4, LA4), CA5 = pack2(LA5, LA5), ONE2 = pack2(1.f, 1.f);
    u64 acc = 0;                        // packed {0.f, 0.f}
    int stride = gridDim.x * blockDim.x;
    for (int i = blockIdx.x * blockDim.x + threadIdx.x; i < TOTAL4; i += stride) {
        unsigned bp = (unsigned)i / 20u;           // 20 float4 per prior
        if (g_valid[bp]) {
            float4 v = conf4[i];
            acc = g0pair_acc(v.x, v.y, acc, CA1, CA2, CA3, CA4, CA5, ONE2);
            acc = g0pair_acc(v.z, v.w, acc, CA1, CA2, CA3, CA4, CA5, ONE2);
        }
    }
    float a0, a1; unpack2(acc, a0, a1);
    float s = a0 + a1;
    #pragma unroll
    for (int o = 16; o; o >>= 1) s += __shfl_down_sync(0xFFFFFFFFu, s, o);
    __shared__ float s_a[8];
    int wid = threadIdx.x >> 5, lane = threadIdx.x & 31;
    if (lane == 0) s_a[wid] = s;
    __syncthreads();
    if (wid == 0) {
        s = (lane < 8) ? s_a[lane] : 0.f;
        #pragma unroll
        for (int o = 4; o; o >>= 1) s += __shfl_down_sync(0xFFFFFFFFu, s, o);
        if (lane == 0) atomicAdd(&g_sum_lcraw, s);
    }
}

// finalize AND reset scratch for the next graph replay
__global__ void k_final(float* __restrict__ out) {
    int i = threadIdx.x;
    if (i == 0) {
        float pn = fmaxf((float)g_poscnt, 1.0f);
        out[0] = g_sum_ll / (pn * 4.0f);
        out[1] = (0.75f * g_sum_lcraw + g_sum_corr) / pn;
        g_sum_ll = 0.f; g_sum_lcraw = 0.f; g_sum_corr = 0.f; g_poscnt = 0;
    }
    if (i < B * O) g_bestprior[i] = 0ull;
}

// ---------------- launch ----------------
extern "C" void kernel_launch(void* const* d_in, const int* in_sizes, int n_in,
                              void* d_out, int out_size) {
    const float4* loc4    = (const float4*)d_in[0];   // (B,P,4)  f32
    const float4* conf4   = (const float4*)d_in[1];   // (B,P,80) f32
    const float*  conf    = (const float*)d_in[1];
    const float4* priors4 = (const float4*)d_in[2];   // (P,4)    f32
    const float*  targets = (const float*)d_in[3];    // (B,O,5)  f32
    float* out = (float*)d_out;

    dim3 mg(P / 256, B);
    k_match<<<mg, 256>>>(priors4, targets, conf, loc4);
    k_patch<<<1, B * O>>>(priors4, targets, conf, loc4);
    k_loss<<<1184, 256>>>(conf4);
    k_final<<<1, 512>>>(out);
}

// round 4
// speedup vs baseline: 1.0011x; 1.0011x over previous
#include <cuda_runtime.h>

typedef unsigned long long u64;

#define B  32
#define P  16384
#define O  16
#define NC 80

// ---------------- device scratch (no allocations allowed) ----------------
__device__ float g_overlap[B * P];     // pre-override best IoU (for patch)
__device__ int   g_bidx[B * P];        // pre-override best truth (for patch)
__device__ u64   g_bestprior[B * O];
__device__ float g_sum_ll;             // loc loss sum
__device__ float g_sum_lcraw;          // sum of sigmoid*softplus (t=0 raw form)
__device__ float g_sum_corr;           // target-class corrections (true units)
__device__ int   g_poscnt;

// ---------------- math helpers ----------------
__device__ __forceinline__ float frcp(float a) {
    float r; asm("rcp.approx.f32 %0, %1;" : "=f"(r) : "f"(a)); return r;
}

// A&S 4.1.43: ln(1+s) = s*(A1+s*(A2+s*(A3+s*(A4+s*A5)))), |err|<=1e-5 on [0,1]
#define LA1 0.99949556f
#define LA2 (-0.49190896f)
#define LA3 0.28947478f
#define LA4 (-0.13606275f)
#define LA5 0.03215845f

// fast g0(x) = softplus(x)*sigmoid(x): 2 MUFU (ex2, rcp), no divide, no log
__device__ __forceinline__ float g0fast_acc(float x, float acc) {
    float s = __expf(-fabsf(x));                     // exp(-|x|) in (0,1]
    float r = frcp(1.0f + s);
    float q = ((x >= 0.f) ? s : 1.0f) * r;           // sigmoid(-x)
    float L = s * fmaf(s, fmaf(s, fmaf(s, fmaf(s, LA5, LA4), LA3), LA2), LA1);
    float h = fmaxf(x, 0.f) + L;                     // softplus(x)
    return fmaf(h, -q, acc + h);                     // acc + h*(1-q)
}

__device__ __forceinline__ float g0raw(float x) {    // precise (cold paths)
    float e = __expf(-fabsf(x));
    float L = __logf(1.0f + e);
    float h = fmaxf(x, 0.0f) + L;
    float q = __expf(-h);
    return fmaf(-h, q, h);
}

__device__ __forceinline__ float bl1(float diff) {
    const float bb = 19.085537f;                     // e^3 - 1
    float d = fabsf(diff);
    if (d < 0.11f) {
        return (0.5f / bb) * (bb * d + 1.f) * log1pf(bb * d * (1.0f / 0.11f)) - 0.5f * d;
    }
    return 1.5f * d + (1.5f / bb - 0.5f * 0.11f);
}

// loc loss + focal target-class correction for a positive prior (b, truth j, prior p)
__device__ __forceinline__ void pos_meta(int b, int j, int p, int bp,
                                         const float4* __restrict__ priors,
                                         const float*  __restrict__ targets,
                                         const float*  __restrict__ conf,
                                         const float4* __restrict__ loc4,
                                         float& ll, float& corr) {
    const float* t = targets + (b * O + j) * 5;
    float m0 = t[0], m1 = t[1], m2 = t[2], m3 = t[3];
    int tc = (int)t[4] + 1;                          // 1..80
    float4 pp = priors[p];
    float ex = ((m0 + m2) * 0.5f - pp.x) / (0.1f * pp.z);
    float ey = ((m1 + m3) * 0.5f - pp.y) / (0.1f * pp.w);
    float ew = __logf((m2 - m0) / pp.z) * 5.0f;
    float eh = __logf((m3 - m1) / pp.w) * 5.0f;
    float4 ld = loc4[bp];
    ll = bl1(ld.x - ex) + bl1(ld.y - ey) + bl1(ld.z - ew) + bl1(ld.w - eh);
    float x = conf[bp * NC + (tc - 1)];
    corr = 0.25f * g0raw(-x) - 0.75f * g0raw(x);     // focal(x,1) - focal(x,0)
}

// ---------------- fused kernel: match + meta + conf stream ----------------
// grid = (P/256, B), block = 256. Block handles priors [p0, p0+256) of batch b:
// phase 1 matches them (valid kept in smem), phase 2 streams their 5120 conf float4.
__global__ void __launch_bounds__(256) k_fused(const float4* __restrict__ priors,
                                               const float*  __restrict__ targets,
                                               const float4* __restrict__ conf4,
                                               const float*  __restrict__ conf,
                                               const float4* __restrict__ loc4) {
    __shared__ float4        s_tr[O];
    __shared__ float         s_area[O];
    __shared__ u64           s_key[O];
    __shared__ unsigned char s_valid[256];

    int tid = threadIdx.x;
    int b   = blockIdx.y;
    int p   = blockIdx.x * blockDim.x + tid;

    if (tid < O) {
        const float* t = targets + (b * O + tid) * 5;
        float4 tr = make_float4(t[0], t[1], t[2], t[3]);   // already point-form
        s_tr[tid]   = tr;
        s_area[tid] = (tr.z - tr.x) * (tr.w - tr.y);
        s_key[tid]  = 0ull;
    }
    __syncthreads();

    // ---- phase 1: match ----
    float4 pr = priors[p];
    float px0 = pr.x - pr.z * 0.5f;
    float py0 = pr.y - pr.w * 0.5f;
    float px1 = pr.x + pr.z * 0.5f;
    float py1 = pr.y + pr.w * 0.5f;
    float areaB = (px1 - px0) * (py1 - py0);

    float best = -1.f;
    int   bidx = 0;
    #pragma unroll
    for (int j = 0; j < O; j++) {
        float4 tr = s_tr[j];
        float ix = fmaxf(fminf(tr.z, px1) - fmaxf(tr.x, px0), 0.f);
        float iy = fmaxf(fminf(tr.w, py1) - fmaxf(tr.y, py0), 0.f);
        float inter = ix * iy;
        float iou   = inter / (s_area[j] + areaB - inter);
        if (iou > best) { best = iou; bidx = j; }          // first-max (JAX argmax)
        u64 key = ((u64)__float_as_uint(iou) << 32) |
                  (unsigned)(0xFFFFFFFFu - (unsigned)p);   // ties -> smallest p
        if (key > s_key[j]) atomicMax(&s_key[j], key);
    }

    int bp = b * P + p;
    g_overlap[bp] = best;
    g_bidx[bp]    = bidx;

    bool pos   = best >= 0.5f;
    bool valid = pos || (best < 0.4f);
    s_valid[tid] = valid ? 1 : 0;

    float ll = 0.f, corr = 0.f;
    int pc = 0;
    if (pos) {
        pc = 1;
        pos_meta(b, bidx, p, bp, priors, targets, conf, loc4, ll, corr);
    }

    // flush per-truth best-prior keys
    __syncthreads();
    if (tid < O) {
        u64 key = s_key[tid];
        if (key > g_bestprior[b * O + tid]) atomicMax(&g_bestprior[b * O + tid], key);
    }

    // ---- phase 2: stream this block's conf rows (valid from smem; no patch dep) ----
    float lc = 0.f;
    long base4 = (long)(b * P + blockIdx.x * 256) * 20;    // 20 float4 per prior
    #pragma unroll 4
    for (int k = 0; k < 20; k++) {
        int le = k * 256 + tid;                            // local element in [0,5120)
        if (s_valid[(unsigned)le / 20u]) {
            float4 v = __ldcs(&conf4[base4 + le]);
            lc = g0fast_acc(v.x, lc);
            lc = g0fast_acc(v.y, lc);
            lc = g0fast_acc(v.z, lc);
            lc = g0fast_acc(v.w, lc);
        }
    }

    // ---- block reduction of (lc, ll, corr, pc), one atomic set per block ----
    #pragma unroll
    for (int o = 16; o; o >>= 1) {
        lc   += __shfl_down_sync(0xFFFFFFFFu, lc, o);
        ll   += __shfl_down_sync(0xFFFFFFFFu, ll, o);
        corr += __shfl_down_sync(0xFFFFFFFFu, corr, o);
        pc   += __shfl_down_sync(0xFFFFFFFFu, pc, o);
    }
    __shared__ float s_lc[8], s_ll[8], s_co[8];
    __shared__ int   s_pc[8];
    int wid = tid >> 5, lane = tid & 31;
    if (lane == 0) { s_lc[wid] = lc; s_ll[wid] = ll; s_co[wid] = corr; s_pc[wid] = pc; }
    __syncthreads();
    if (wid == 0) {
        lc   = (lane < 8) ? s_lc[lane] : 0.f;
        ll   = (lane < 8) ? s_ll[lane] : 0.f;
        corr = (lane < 8) ? s_co[lane] : 0.f;
        pc   = (lane < 8) ? s_pc[lane] : 0;
        #pragma unroll
        for (int o = 4; o; o >>= 1) {
            lc   += __shfl_down_sync(0xFFFFFFFFu, lc, o);
            ll   += __shfl_down_sync(0xFFFFFFFFu, ll, o);
            corr += __shfl_down_sync(0xFFFFFFFFu, corr, o);
            pc   += __shfl_down_sync(0xFFFFFFFFu, pc, o);
        }
        if (lane == 0) {
            atomicAdd(&g_sum_lcraw, lc);
            if (pc) {
                atomicAdd(&g_sum_ll, ll);
                atomicAdd(&g_sum_corr, corr);
                atomicAdd(&g_poscnt, pc);
            }
        }
    }
}

// ---------------- patch + finalize (one block of 512 = B*O) ----------------
__global__ void k_patchfinal(const float4* __restrict__ priors,
                             const float*  __restrict__ targets,
                             const float*  __restrict__ conf,
                             const float4* __restrict__ loc4,
                             float* __restrict__ out) {
    __shared__ unsigned s_p[B * O];
    __shared__ float    s_dll, s_dcorr, s_dlcraw;
    __shared__ int      s_dpc;

    int tid = threadIdx.x;
    int b = tid >> 4, j = tid & 15;
    if (tid == 0) { s_dll = 0.f; s_dcorr = 0.f; s_dlcraw = 0.f; s_dpc = 0; }

    u64 key = g_bestprior[b * O + j];
    unsigned p = 0xFFFFFFFFu - (unsigned)(key & 0xFFFFFFFFull);
    s_p[tid] = p;
    g_bestprior[b * O + j] = 0ull;          // reset for next replay
    __syncthreads();

    bool apply = true;                      // XLA scatter: last truth targeting p wins
    for (int j2 = j + 1; j2 < O; j2++)
        if (s_p[(b << 4) | j2] == p) apply = false;

    if (apply) {
        int bp = b * P + (int)p;
        float oldov  = g_overlap[bp];
        int   oldj   = g_bidx[bp];
        bool  oldpos = oldov >= 0.5f;
        bool  oldvalid = oldpos || (oldov < 0.4f);

        float ll_n, corr_n;
        pos_meta(b, j, (int)p, bp, priors, targets, conf, loc4, ll_n, corr_n);
        float dll = ll_n, dcorr = corr_n, dlcraw = 0.f;
        int dpc = 1;
        if (oldpos) {                       // remove contribution k_fused already added
            float ll_o, corr_o;
            pos_meta(b, oldj, (int)p, bp, priors, targets, conf, loc4, ll_o, corr_o);
            dll -= ll_o; dcorr -= corr_o; dpc = 0;
        }
        if (!oldvalid) {                    // row was skipped in the base stream: add it
            const float* row = conf + (long)bp * NC;
            float s = 0.f;
            #pragma unroll 4
            for (int c = 0; c < NC; c++) s = g0fast_acc(row[c], s);
            dlcraw = s;
        }
        atomicAdd(&s_dll, dll);
        atomicAdd(&s_dcorr, dcorr);
        if (dlcraw != 0.f) atomicAdd(&s_dlcraw, dlcraw);
        if (dpc) atomicAdd(&s_dpc, dpc);
    }
    __syncthreads();

    if (tid == 0) {
        float pn = fmaxf((float)(g_poscnt + s_dpc), 1.0f);
        out[0] = (g_sum_ll + s_dll) / (pn * 4.0f);
        out[1] = (0.75f * (g_sum_lcraw + s_dlcraw) + g_sum_corr + s_dcorr) / pn;
        g_sum_ll = 0.f; g_sum_lcraw = 0.f; g_sum_corr = 0.f; g_poscnt = 0;
    }
}

// ---------------- launch ----------------
extern "C" void kernel_launch(void* const* d_in, const int* in_sizes, int n_in,
                              void* d_out, int out_size) {
    const float4* loc4    = (const float4*)d_in[0];   // (B,P,4)  f32
    const float4* conf4   = (const float4*)d_in[1];   // (B,P,80) f32
    const float*  conf    = (const float*)d_in[1];
    const float4* priors4 = (const float4*)d_in[2];   // (P,4)    f32
    const float*  targets = (const float*)d_in[3];    // (B,O,5)  f32
    float* out = (float*)d_out;

    dim3 g(P / 256, B);                               // 2048 blocks
    k_fused<<<g, 256>>>(priors4, targets, conf4, conf, loc4);
    k_patchfinal<<<1, B * O>>>(priors4, targets, conf, loc4, out);
}